// round 6
// baseline (speedup 1.0000x reference)
#include <cuda_runtime.h>
#include <math.h>

// FlashAttentionNaive on GB300 — R1: fp32 CUDA-core register-tiled flash kernel.
// (b=2,h=16,s=2048,d=128), causal, B_C=128. Reproduces the reference's
// quirky recurrence via U = O*l:  U' = e_i*U + e_ij*(P@V),  l' = e_i*l + sum(P).

#define D    128
#define BQ   128
#define BC   128
#define SEQ  2048
#define NQT  (SEQ / BQ)   // 16
#define BH   32           // b*h
#define SST  129          // padded smem row stride (floats)
#define SMEM_BYTES (3 * BQ * SST * 4)

__global__ __launch_bounds__(256, 1)
void fa_naive_kernel(const float* __restrict__ Qg_,
                     const float* __restrict__ Kg_,
                     const float* __restrict__ Vg_,
                     float* __restrict__ Og_)
{
    extern __shared__ float sm[];
    float* Qs = sm;                 // [BQ][SST]
    float* Ks = sm + BQ * SST;      // [BC][SST], reused for P' between GEMMs
    float* Vs = sm + 2 * BQ * SST;  // [BC][SST]

    const int bid = blockIdx.x;
    const int qt  = (NQT - 1) - (bid >> 5);  // heavy tiles first
    const int bh  = bid & 31;

    const int tid = threadIdx.x;
    const int tx  = tid & 15;   // col group
    const int ty  = tid >> 4;   // row group

    const float scale = 0.08838834764831843f;  // 1/sqrt(128)

    const size_t base = (size_t)bh * (SEQ * D);
    const float* Qg = Qg_ + base + (size_t)(qt * BQ) * D;
    const float* Kg = Kg_ + base;
    const float* Vg = Vg_ + base;
    float*       Og = Og_ + base + (size_t)(qt * BQ) * D;

    // ---- load Q tile (coalesced LDG.32, conflict-free STS) ----
    {
        const int r0 = tid >> 7;       // 0..1
        const int c  = tid & 127;
        #pragma unroll
        for (int r = 0; r < BQ; r += 2)
            Qs[(r + r0) * SST + c] = Qg[(r + r0) * D + c];
    }

    float m_i[8], l_i[8], U[8][8];
    #pragma unroll
    for (int i = 0; i < 8; i++) {
        m_i[i] = -INFINITY;
        l_i[i] = 0.f;
        #pragma unroll
        for (int j = 0; j < 8; j++) U[i][j] = 0.f;
    }

    const int nblk = qt + 1;  // blocks beyond the diagonal are exact no-ops
    for (int jb = 0; jb < nblk; jb++) {
        __syncthreads();  // prior iter's smem reads done (also covers Qs on iter 0)

        // ---- load K,V blocks ----
        {
            const int r0 = tid >> 7;
            const int c  = tid & 127;
            const float* Kb = Kg + (size_t)(jb * BC) * D;
            const float* Vb = Vg + (size_t)(jb * BC) * D;
            #pragma unroll
            for (int r = 0; r < BC; r += 2) {
                Ks[(r + r0) * SST + c] = Kb[(r + r0) * D + c];
                Vs[(r + r0) * SST + c] = Vb[(r + r0) * D + c];
            }
        }
        __syncthreads();

        // ---- S = Q @ K^T (rows ty+16i, cols tx+16j) ----
        float S[8][8];
        #pragma unroll
        for (int i = 0; i < 8; i++)
            #pragma unroll
            for (int j = 0; j < 8; j++) S[i][j] = 0.f;

        #pragma unroll 4
        for (int k = 0; k < D; k++) {
            float a[8], b[8];
            #pragma unroll
            for (int i = 0; i < 8; i++) a[i] = Qs[(ty + 16 * i) * SST + k];
            #pragma unroll
            for (int j = 0; j < 8; j++) b[j] = Ks[(tx + 16 * j) * SST + k];
            #pragma unroll
            for (int i = 0; i < 8; i++)
                #pragma unroll
                for (int j = 0; j < 8; j++)
                    S[i][j] = fmaf(a[i], b[j], S[i][j]);
        }

        // ---- scale + causal mask (only diagonal block partially masked) ----
        const bool diag = (jb == qt);
        #pragma unroll
        for (int i = 0; i < 8; i++)
            #pragma unroll
            for (int j = 0; j < 8; j++) {
                float v = S[i][j] * scale;
                if (diag && (tx + 16 * j) > (ty + 16 * i)) v = -INFINITY;
                S[i][j] = v;
            }

        // ---- online softmax state (16-lane shuffle reductions over tx) ----
        float mb[8], e_i[8], e_b[8];
        #pragma unroll
        for (int i = 0; i < 8; i++) {
            float m = S[i][0];
            #pragma unroll
            for (int j = 1; j < 8; j++) m = fmaxf(m, S[i][j]);
            #pragma unroll
            for (int off = 1; off < 16; off <<= 1)
                m = fmaxf(m, __shfl_xor_sync(0xffffffffu, m, off));
            mb[i] = m;
        }
        #pragma unroll
        for (int i = 0; i < 8; i++) {
            const float mnew = fmaxf(m_i[i], mb[i]);
            float rs = 0.f;
            #pragma unroll
            for (int j = 0; j < 8; j++) {
                const float p = __expf(S[i][j] - mnew);  // exp(-inf)=0 handles mask
                S[i][j] = p;
                rs += p;
            }
            #pragma unroll
            for (int off = 1; off < 16; off <<= 1)
                rs += __shfl_xor_sync(0xffffffffu, rs, off);
            e_i[i] = __expf(m_i[i] - mnew);
            e_b[i] = __expf(mb[i] - mnew);   // the reference's extra factor
            l_i[i] = e_i[i] * l_i[i] + rs;
            m_i[i] = mnew;
        }

        __syncthreads();  // everyone done reading Ks -> safe to overwrite with P'
        #pragma unroll
        for (int i = 0; i < 8; i++) {
            #pragma unroll
            for (int j = 0; j < 8; j++) {
                Ks[(ty + 16 * i) * SST + (tx + 16 * j)] = e_b[i] * S[i][j];
                U[i][j] *= e_i[i];
            }
        }
        __syncthreads();

        // ---- U += P' @ V ----
        #pragma unroll 4
        for (int k = 0; k < BC; k++) {
            float a[8], b[8];
            #pragma unroll
            for (int i = 0; i < 8; i++) a[i] = Ks[(ty + 16 * i) * SST + k];
            #pragma unroll
            for (int j = 0; j < 8; j++) b[j] = Vs[k * SST + (tx + 16 * j)];
            #pragma unroll
            for (int i = 0; i < 8; i++)
                #pragma unroll
                for (int j = 0; j < 8; j++)
                    U[i][j] = fmaf(a[i], b[j], U[i][j]);
        }
    }

    // ---- epilogue: O = U / l ----
    #pragma unroll
    for (int i = 0; i < 8; i++) {
        const float inv = 1.f / l_i[i];
        #pragma unroll
        for (int j = 0; j < 8; j++)
            Og[(ty + 16 * i) * D + (tx + 16 * j)] = U[i][j] * inv;
    }
}

extern "C" void kernel_launch(void* const* d_in, const int* in_sizes, int n_in,
                              void* d_out, int out_size)
{
    const float* Q = (const float*)d_in[0];
    const float* K = (const float*)d_in[1];
    const float* V = (const float*)d_in[2];
    float*       O = (float*)d_out;

    cudaFuncSetAttribute(fa_naive_kernel,
                         cudaFuncAttributeMaxDynamicSharedMemorySize, SMEM_BYTES);
    fa_naive_kernel<<<BH * NQT, 256, SMEM_BYTES>>>(Q, K, V, O);
}

// round 8
// speedup vs baseline: 2.6829x; 2.6829x over previous
#include <cuda_runtime.h>
#include <cstdint>
#include <math.h>

// FlashAttentionNaive on GB300 — R7: mma.sync tf32 (portable tensor path; tcgen05 is
// arch-'a'-gated and the harness compiles at compute_103, so it's unavailable).
// (b=2,h=16,s=2048,d=128), causal, B_C=128.
// Reference recurrence via U = O*l:  U' = e_i*U + e_b*(P@V), l' = e_i*l + sum(P), O = U/l.

#define SEQ 2048
#define DH  128
#define BQ  128
#define BC  128
#define NQT 16
#define BH  32

#define SQK 132   // Q/K/P smem row stride (floats) -> conflict-free frag LDS
#define SV  136   // V smem row stride (floats)     -> conflict-free frag LDS

// smem layout in floats
#define QOFF 0
#define KOFF (BQ * SQK)            // K tile, reused as P' buffer
#define VOFF (KOFF + BC * SQK)
#define XOFF (VOFF + BC * SV)      // smax[2][128]
#define SOFF (XOFF + 256)          // ssum[2][128]
#define SM_FLOATS (SOFF + 256)
#define SMEM_BYTES (SM_FLOATS * 4)

// softmax in base-2 domain: scale * log2(e)
#define SL2E 0.12751744f

static __device__ __forceinline__ float cvt_tf32(float x) {
    float r; asm("cvt.rna.tf32.f32 %0, %1;" : "=f"(r) : "f"(x)); return r;
}

// fast exp2 on FMA pipe (no MUFU): rel err ~2e-6, input clamped at -126
static __device__ __forceinline__ float exp2f_fast(float x) {
    x = fmaxf(x, -126.0f);
    float t = x + 12582912.0f;               // round-to-nearest int in mantissa
    int   n = __float_as_int(t);
    float f = x - (t - 12582912.0f);         // frac in [-0.5, 0.5]
    float p = 1.3333558e-3f;
    p = fmaf(p, f, 9.6181291e-3f);
    p = fmaf(p, f, 5.5504109e-2f);
    p = fmaf(p, f, 2.4022651e-1f);
    p = fmaf(p, f, 6.9314718e-1f);
    p = fmaf(p, f, 1.0f);
    return p * __int_as_float((n - 0x4B400000 + 127) << 23);
}

// m16n8k8 row.col tf32 mma, D += A*B (accumulate in place)
static __device__ __forceinline__ void mma8(float* d, const float* a, float b0, float b1) {
    asm volatile(
        "mma.sync.aligned.m16n8k8.row.col.f32.tf32.tf32.f32 "
        "{%0,%1,%2,%3}, {%4,%5,%6,%7}, {%8,%9}, {%0,%1,%2,%3};"
        : "+f"(d[0]), "+f"(d[1]), "+f"(d[2]), "+f"(d[3])
        : "r"(__float_as_uint(a[0])), "r"(__float_as_uint(a[1])),
          "r"(__float_as_uint(a[2])), "r"(__float_as_uint(a[3])),
          "r"(__float_as_uint(b0)),  "r"(__float_as_uint(b1)));
}

// 128x128 global tile -> smem (stride dstride), tf32-rounded, coalesced LDG.128/STS.128
static __device__ __forceinline__ void load_tile(float* __restrict__ dst,
                                                 const float* __restrict__ src,
                                                 int dstride, int tid) {
#pragma unroll
    for (int t = 0; t < 16; t++) {
        const int idx = tid + t * 256;
        const int r = idx >> 5, c4 = (idx & 31) << 2;
        float4 v = *(const float4*)(src + (size_t)r * DH + c4);
        v.x = cvt_tf32(v.x); v.y = cvt_tf32(v.y);
        v.z = cvt_tf32(v.z); v.w = cvt_tf32(v.w);
        *(float4*)(dst + r * dstride + c4) = v;
    }
}

__global__ __launch_bounds__(256, 1)
void fa_mma(const float* __restrict__ Qg_, const float* __restrict__ Kg_,
            const float* __restrict__ Vg_, float* __restrict__ Og_)
{
    extern __shared__ float sm[];
    float* Qs   = sm + QOFF;
    float* Ks   = sm + KOFF;   // K tile / P' buffer
    float* Vs   = sm + VOFF;
    float* smax = sm + XOFF;
    float* ssum = sm + SOFF;

    const int tid  = threadIdx.x;
    const int wid  = tid >> 5, lane = tid & 31;
    const int qr   = lane >> 2, qc = lane & 3;
    const int wm   = wid & 3;          // row group of 32
    const int wn   = wid >> 2;         // column half (0: cols 0-63, 1: 64-127)
    const int row0 = wm * 32;
    const int col0 = wn * 64;

    const int bid = blockIdx.x;
    const int qt  = (NQT - 1) - (bid >> 5);  // heavy tiles first
    const int bh  = bid & 31;

    const size_t base = (size_t)bh * SEQ * DH;
    const float* Qg = Qg_ + base + (size_t)qt * BQ * DH;
    const float* Kg = Kg_ + base;
    const float* Vg = Vg_ + base;
    float*       Og = Og_ + base + (size_t)qt * BQ * DH;

    load_tile(Qs, Qg, SQK, tid);

    float U[2][8][4];
#pragma unroll
    for (int mt = 0; mt < 2; mt++)
#pragma unroll
        for (int nt = 0; nt < 8; nt++)
#pragma unroll
            for (int c = 0; c < 4; c++) U[mt][nt][c] = 0.f;

    float m_i[4], l_i[4];
#pragma unroll
    for (int i = 0; i < 4; i++) { m_i[i] = -1e30f; l_i[i] = 0.f; }

    const int nblk = qt + 1;   // blocks past the diagonal are exact no-ops
    for (int jb = 0; jb < nblk; jb++) {
        __syncthreads();  // previous iteration done reading Ks/Vs
        load_tile(Ks, Kg + (size_t)jb * BC * DH, SQK, tid);
        load_tile(Vs, Vg + (size_t)jb * BC * DH, SV,  tid);
        __syncthreads();

        // ---- S = Q @ K^T : warp tile 32x64, 2x8 m16n8k8 frags ----
        float S[2][8][4];
#pragma unroll
        for (int mt = 0; mt < 2; mt++)
#pragma unroll
            for (int nt = 0; nt < 8; nt++)
#pragma unroll
                for (int c = 0; c < 4; c++) S[mt][nt][c] = 0.f;

#pragma unroll
        for (int kt = 0; kt < 16; kt++) {
            const int k0 = kt * 8;
            float a[2][4];
#pragma unroll
            for (int mt = 0; mt < 2; mt++) {
                const float* p = Qs + (row0 + mt * 16 + qr) * SQK + k0 + qc;
                a[mt][0] = p[0];       a[mt][1] = p[8 * SQK];
                a[mt][2] = p[4];       a[mt][3] = p[8 * SQK + 4];
            }
#pragma unroll
            for (int nt = 0; nt < 8; nt++) {
                const float* pb = Ks + (col0 + nt * 8 + qr) * SQK + k0 + qc;
                const float b0 = pb[0], b1 = pb[4];
                mma8(S[0][nt], a[0], b0, b1);
                mma8(S[1][nt], a[1], b0, b1);
            }
        }

        // ---- scale to base-2 domain + causal mask + row max ----
        const bool diag = (jb == qt);
#pragma unroll
        for (int mt = 0; mt < 2; mt++)
#pragma unroll
            for (int h = 0; h < 2; h++) {
                const int rl = row0 + mt * 16 + h * 8 + qr;
                float m = -1e30f;
#pragma unroll
                for (int nt = 0; nt < 8; nt++)
#pragma unroll
                    for (int e = 0; e < 2; e++) {
                        float x = S[mt][nt][2 * h + e] * SL2E;
                        const int cl = col0 + nt * 8 + 2 * qc + e;
                        if (diag && cl > rl) x = -1e30f;
                        S[mt][nt][2 * h + e] = x;
                        m = fmaxf(m, x);
                    }
                m = fmaxf(m, __shfl_xor_sync(0xffffffffu, m, 1));
                m = fmaxf(m, __shfl_xor_sync(0xffffffffu, m, 2));
                smax[wn * 128 + rl] = m;   // 4 lanes write same value
            }
        __syncthreads();

        // ---- exp + row sums + state update ----
        float e_i[4], e_b[4];
#pragma unroll
        for (int mt = 0; mt < 2; mt++)
#pragma unroll
            for (int h = 0; h < 2; h++) {
                const int idx = mt * 2 + h;
                const int rl  = row0 + mt * 16 + h * 8 + qr;
                const float mb   = fmaxf(smax[rl], smax[128 + rl]);
                const float mnew = fmaxf(m_i[idx], mb);
                float rs = 0.f;
#pragma unroll
                for (int nt = 0; nt < 8; nt++)
#pragma unroll
                    for (int e = 0; e < 2; e++) {
                        const float p = exp2f_fast(S[mt][nt][2 * h + e] - mnew);
                        S[mt][nt][2 * h + e] = p;
                        rs += p;
                    }
                rs += __shfl_xor_sync(0xffffffffu, rs, 1);
                rs += __shfl_xor_sync(0xffffffffu, rs, 2);
                ssum[wn * 128 + rl] = rs;
                e_i[idx] = exp2f_fast(m_i[idx] - mnew);
                e_b[idx] = exp2f_fast(mb - mnew);   // reference's extra factor
                m_i[idx] = mnew;
            }
        __syncthreads();

        // ---- l update; store P' = e_b*P (tf32) into K buffer; U *= e_i ----
#pragma unroll
        for (int mt = 0; mt < 2; mt++)
#pragma unroll
            for (int h = 0; h < 2; h++) {
                const int idx = mt * 2 + h;
                const int rl  = row0 + mt * 16 + h * 8 + qr;
                l_i[idx] = e_i[idx] * l_i[idx] + ssum[rl] + ssum[128 + rl];
                const float eb = e_b[idx], ei = e_i[idx];
#pragma unroll
                for (int nt = 0; nt < 8; nt++) {
                    float2 w;
                    w.x = cvt_tf32(eb * S[mt][nt][2 * h]);
                    w.y = cvt_tf32(eb * S[mt][nt][2 * h + 1]);
                    *(float2*)(Ks + rl * SQK + col0 + nt * 8 + 2 * qc) = w;
                    U[mt][nt][2 * h]     *= ei;
                    U[mt][nt][2 * h + 1] *= ei;
                }
            }
        __syncthreads();

        // ---- U += P' @ V ----
#pragma unroll
        for (int kt = 0; kt < 16; kt++) {
            const int k0 = kt * 8;
            float a[2][4];
#pragma unroll
            for (int mt = 0; mt < 2; mt++) {
                const float* p = Ks + (row0 + mt * 16 + qr) * SQK + k0 + qc;
                a[mt][0] = p[0];       a[mt][1] = p[8 * SQK];
                a[mt][2] = p[4];       a[mt][3] = p[8 * SQK + 4];
            }
#pragma unroll
            for (int nt = 0; nt < 8; nt++) {
                const float* pv = Vs + (k0 + qc) * SV + col0 + nt * 8 + qr;
                const float b0 = pv[0], b1 = pv[4 * SV];
                mma8(U[0][nt], a[0], b0, b1);
                mma8(U[1][nt], a[1], b0, b1);
            }
        }
    }

    // ---- epilogue: O = U / l ----
#pragma unroll
    for (int mt = 0; mt < 2; mt++)
#pragma unroll
        for (int h = 0; h < 2; h++) {
            const int idx = mt * 2 + h;
            const int rl  = row0 + mt * 16 + h * 8 + qr;
            const float inv = 1.f / l_i[idx];
#pragma unroll
            for (int nt = 0; nt < 8; nt++) {
                float2 w;
                w.x = U[mt][nt][2 * h] * inv;
                w.y = U[mt][nt][2 * h + 1] * inv;
                *(float2*)(Og + (size_t)rl * DH + col0 + nt * 8 + 2 * qc) = w;
            }
        }
}

extern "C" void kernel_launch(void* const* d_in, const int* in_sizes, int n_in,
                              void* d_out, int out_size)
{
    const float* Q = (const float*)d_in[0];
    const float* K = (const float*)d_in[1];
    const float* V = (const float*)d_in[2];
    float*       O = (float*)d_out;

    cudaFuncSetAttribute(fa_mma, cudaFuncAttributeMaxDynamicSharedMemorySize, SMEM_BYTES);
    fa_mma<<<BH * NQT, 256, SMEM_BYTES>>>(Q, K, V, O);
}

// round 9
// speedup vs baseline: 3.1961x; 1.1913x over previous
#include <cuda_runtime.h>
#include <cstdint>
#include <math.h>

// FlashAttentionNaive on GB300 — R8: mma.sync tf32, 512 threads (16 warps, 4x4 grid),
// cp.async loads with V hidden behind S-GEMM/softmax, one-sync softmax exchange.
// Reference recurrence via U = O*l:  U' = e_i*U + e_b*(P@V), l' = e_i*l + sum(P), O = U/l.

#define SEQ 2048
#define DH  128
#define NQT 16
#define BH  32

#define SQK 132   // Q/K/P' smem row stride (floats): frag bank = 4*qr+qc, conflict-free
#define SV  136   // V smem row stride: frag bank = 8*qc+qr, conflict-free

#define QOFF 0
#define KOFF (128 * SQK)
#define VOFF (KOFF + 128 * SQK)
#define TOFF (VOFF + 128 * SV)     // stat[128][4] float2 = 1024 floats
#define SM_FLOATS (TOFF + 1024)
#define SMEM_BYTES (SM_FLOATS * 4)

// softmax in base-2 domain: (1/sqrt(128)) * log2(e)
#define SL2E 0.12751744f

static __device__ __forceinline__ float cvt_tf32(float x) {
    float r; asm("cvt.rna.tf32.f32 %0, %1;" : "=f"(r) : "f"(x)); return r;
}

// fast exp2 on the FMA pipe (no MUFU): rel err ~2e-6, clamped at -126
static __device__ __forceinline__ float exp2f_fast(float x) {
    x = fmaxf(x, -126.0f);
    float t = x + 12582912.0f;
    int   n = __float_as_int(t);
    float f = x - (t - 12582912.0f);
    float p = 1.3333558e-3f;
    p = fmaf(p, f, 9.6181291e-3f);
    p = fmaf(p, f, 5.5504109e-2f);
    p = fmaf(p, f, 2.4022651e-1f);
    p = fmaf(p, f, 6.9314718e-1f);
    p = fmaf(p, f, 1.0f);
    return p * __int_as_float((n - 0x4B400000 + 127) << 23);
}

static __device__ __forceinline__ void mma8(float* d, const float* a, float b0, float b1) {
    asm volatile(
        "mma.sync.aligned.m16n8k8.row.col.f32.tf32.tf32.f32 "
        "{%0,%1,%2,%3}, {%4,%5,%6,%7}, {%8,%9}, {%0,%1,%2,%3};"
        : "+f"(d[0]), "+f"(d[1]), "+f"(d[2]), "+f"(d[3])
        : "r"(__float_as_uint(a[0])), "r"(__float_as_uint(a[1])),
          "r"(__float_as_uint(a[2])), "r"(__float_as_uint(a[3])),
          "r"(__float_as_uint(b0)),  "r"(__float_as_uint(b1)));
}

#define CP_ASYNC16(dst32, src) \
    asm volatile("cp.async.cg.shared.global [%0], [%1], 16;" :: "r"(dst32), "l"(src))
#define CP_COMMIT() asm volatile("cp.async.commit_group;")
#define CP_WAIT(N)  asm volatile("cp.async.wait_group %0;" :: "n"(N))

// async-copy one 128x128 f32 tile into smem (row stride dstride), 8 x 16B per thread
static __device__ __forceinline__ void tile_cp_async(float* dst, const float* src,
                                                     int dstride, int tid) {
#pragma unroll
    for (int t = 0; t < 8; t++) {
        const int idx = tid + t * 512;
        const int r = idx >> 5, c4 = (idx & 31) << 2;
        uint32_t d = (uint32_t)__cvta_generic_to_shared(dst + r * dstride + c4);
        CP_ASYNC16(d, src + (size_t)r * DH + c4);
    }
}

__global__ __launch_bounds__(512, 1)
void fa_mma2(const float* __restrict__ Qg_, const float* __restrict__ Kg_,
             const float* __restrict__ Vg_, float* __restrict__ Og_)
{
    extern __shared__ float sm[];
    float* Qs = sm + QOFF;
    float* Ks = sm + KOFF;   // K tile, reused as P' buffer
    float* Vs = sm + VOFF;
    float* st = sm + TOFF;   // stat[rl][seg] float2 = (m_seg, sum_seg)

    const int tid  = threadIdx.x;
    const int lane = tid & 31;
    const int wid  = tid >> 5;
    const int wm   = wid & 3;        // row group (32 rows)
    const int wn   = wid >> 2;       // col group (32 cols)
    const int qr   = lane >> 2, qc = lane & 3;
    const int row0 = wm * 32, col0 = wn * 32;

    const int bid = blockIdx.x;
    const int qt  = (NQT - 1) - (bid >> 5);   // heavy tiles first
    const int bh  = bid & 31;

    const size_t base = (size_t)bh * SEQ * DH;
    const float* Qg = Qg_ + base + (size_t)qt * 128 * DH;
    const float* Kg = Kg_ + base;
    const float* Vg = Vg_ + base;
    float*       Og = Og_ + base + (size_t)qt * 128 * DH;

    // ---- Q load (cp.async) + in-place tf32 round ----
    tile_cp_async(Qs, Qg, SQK, tid);
    CP_COMMIT();
    CP_WAIT(0);
    __syncthreads();
#pragma unroll
    for (int t = 0; t < 8; t++) {
        const int idx = tid + t * 512;
        const int r = idx >> 5, c4 = (idx & 31) << 2;
        float4* p = (float4*)(Qs + r * SQK + c4);
        float4 v = *p;
        v.x = cvt_tf32(v.x); v.y = cvt_tf32(v.y);
        v.z = cvt_tf32(v.z); v.w = cvt_tf32(v.w);
        *p = v;
    }

    float U[2][4][4];
#pragma unroll
    for (int mt = 0; mt < 2; mt++)
#pragma unroll
        for (int nt = 0; nt < 4; nt++)
#pragma unroll
            for (int c = 0; c < 4; c++) U[mt][nt][c] = 0.f;
    float m_i[4], l_i[4];
#pragma unroll
    for (int i = 0; i < 4; i++) { m_i[i] = -1e30f; l_i[i] = 0.f; }

    const int nblk = qt + 1;   // blocks past the diagonal are exact no-ops
    for (int jb = 0; jb < nblk; jb++) {
        __syncthreads();  // prior iteration done reading Ks/Vs (and Q-cvt on iter 0)

        // K group, then V group; only wait K now — V hides behind S-GEMM + softmax
        tile_cp_async(Ks, Kg + (size_t)jb * 128 * DH, SQK, tid);
        CP_COMMIT();
        tile_cp_async(Vs, Vg + (size_t)jb * 128 * DH, SV, tid);
        CP_COMMIT();
        CP_WAIT(1);
        __syncthreads();

        // ---- S = Q @ K^T : warp tile 32x32, 2x4 m16n8k8 frags ----
        float S[2][4][4];
#pragma unroll
        for (int mt = 0; mt < 2; mt++)
#pragma unroll
            for (int nt = 0; nt < 4; nt++)
#pragma unroll
                for (int c = 0; c < 4; c++) S[mt][nt][c] = 0.f;

#pragma unroll
        for (int kt = 0; kt < 16; kt++) {
            const int k0 = kt * 8;
            float a[2][4];
#pragma unroll
            for (int mt = 0; mt < 2; mt++) {
                const float* p = Qs + (row0 + mt * 16 + qr) * SQK + k0 + qc;
                a[mt][0] = p[0];   a[mt][1] = p[8 * SQK];
                a[mt][2] = p[4];   a[mt][3] = p[8 * SQK + 4];
            }
#pragma unroll
            for (int nt = 0; nt < 4; nt++) {
                const float* pb = Ks + (col0 + nt * 8 + qr) * SQK + k0 + qc;
                const float b0 = pb[0], b1 = pb[4];
                mma8(S[0][nt], a[0], b0, b1);
                mma8(S[1][nt], a[1], b0, b1);
            }
        }

        // ---- scale to base-2 (+ causal mask only on the diagonal block) ----
        if (jb == qt) {
#pragma unroll
            for (int mt = 0; mt < 2; mt++)
#pragma unroll
                for (int h = 0; h < 2; h++) {
                    const int rl = row0 + mt * 16 + h * 8 + qr;
#pragma unroll
                    for (int nt = 0; nt < 4; nt++)
#pragma unroll
                        for (int e = 0; e < 2; e++) {
                            float x = S[mt][nt][2 * h + e] * SL2E;
                            if ((col0 + nt * 8 + 2 * qc + e) > rl) x = -1e30f;
                            S[mt][nt][2 * h + e] = x;
                        }
                }
        } else {
#pragma unroll
            for (int mt = 0; mt < 2; mt++)
#pragma unroll
                for (int nt = 0; nt < 4; nt++)
#pragma unroll
                    for (int c = 0; c < 4; c++)
                        S[mt][nt][c] *= SL2E;
        }

        // ---- local (32-col segment) softmax: max, exp vs local max, sum ----
#pragma unroll
        for (int mt = 0; mt < 2; mt++)
#pragma unroll
            for (int h = 0; h < 2; h++) {
                const int rl = row0 + mt * 16 + h * 8 + qr;
                float m = -1e30f;
#pragma unroll
                for (int nt = 0; nt < 4; nt++)
#pragma unroll
                    for (int e = 0; e < 2; e++)
                        m = fmaxf(m, S[mt][nt][2 * h + e]);
                m = fmaxf(m, __shfl_xor_sync(0xffffffffu, m, 1));
                m = fmaxf(m, __shfl_xor_sync(0xffffffffu, m, 2));
                float rs = 0.f;
#pragma unroll
                for (int nt = 0; nt < 4; nt++)
#pragma unroll
                    for (int e = 0; e < 2; e++) {
                        const float p = exp2f_fast(S[mt][nt][2 * h + e] - m);
                        S[mt][nt][2 * h + e] = p;
                        rs += p;
                    }
                rs += __shfl_xor_sync(0xffffffffu, rs, 1);
                rs += __shfl_xor_sync(0xffffffffu, rs, 2);
                if (qc == 0)
                    *(float2*)(st + rl * 8 + wn * 2) = make_float2(m, rs);
            }
        __syncthreads();

        // ---- combine segments, update state, store P' (into K buffer), scale U ----
#pragma unroll
        for (int mt = 0; mt < 2; mt++)
#pragma unroll
            for (int h = 0; h < 2; h++) {
                const int idx = mt * 2 + h;
                const int rl  = row0 + mt * 16 + h * 8 + qr;
                const float2 s0 = *(const float2*)(st + rl * 8 + 0);
                const float2 s1 = *(const float2*)(st + rl * 8 + 2);
                const float2 s2 = *(const float2*)(st + rl * 8 + 4);
                const float2 s3 = *(const float2*)(st + rl * 8 + 6);
                const float mb   = fmaxf(fmaxf(s0.x, s1.x), fmaxf(s2.x, s3.x));
                const float mnew = fmaxf(m_i[idx], mb);
                const float f0 = exp2f_fast(s0.x - mnew);
                const float f1 = exp2f_fast(s1.x - mnew);
                const float f2 = exp2f_fast(s2.x - mnew);
                const float f3 = exp2f_fast(s3.x - mnew);
                const float rtot = fmaf(s0.y, f0, fmaf(s1.y, f1, fmaf(s2.y, f2, s3.y * f3)));
                const float e_i = exp2f_fast(m_i[idx] - mnew);
                const float e_b = exp2f_fast(mb - mnew);      // reference's extra factor
                l_i[idx] = e_i * l_i[idx] + rtot;
                m_i[idx] = mnew;
                const float fown = (wn == 0) ? f0 : (wn == 1) ? f1 : (wn == 2) ? f2 : f3;
                const float fac  = e_b * fown;                // P' = fac * p_local
#pragma unroll
                for (int nt = 0; nt < 4; nt++) {
                    float2 w;
                    w.x = fac * S[mt][nt][2 * h];
                    w.y = fac * S[mt][nt][2 * h + 1];
                    *(float2*)(Ks + rl * SQK + col0 + nt * 8 + 2 * qc) = w;
                    U[mt][nt][2 * h]     *= e_i;
                    U[mt][nt][2 * h + 1] *= e_i;
                }
            }
        CP_WAIT(0);      // V tile arrived (hidden behind S-GEMM + softmax)
        __syncthreads();

        // ---- U += P' @ V ----
#pragma unroll
        for (int kt = 0; kt < 16; kt++) {
            const int k0 = kt * 8;
            float a[2][4];
#pragma unroll
            for (int mt = 0; mt < 2; mt++) {
                const float* p = Ks + (row0 + mt * 16 + qr) * SQK + k0 + qc;
                a[mt][0] = p[0];   a[mt][1] = p[8 * SQK];
                a[mt][2] = p[4];   a[mt][3] = p[8 * SQK + 4];
            }
#pragma unroll
            for (int nt = 0; nt < 4; nt++) {
                const float* pv = Vs + (k0 + qc) * SV + col0 + nt * 8 + qr;
                const float b0 = pv[0], b1 = pv[4 * SV];
                mma8(U[0][nt], a[0], b0, b1);
                mma8(U[1][nt], a[1], b0, b1);
            }
        }
    }

    // ---- epilogue: O = U / l ----
#pragma unroll
    for (int mt = 0; mt < 2; mt++)
#pragma unroll
        for (int h = 0; h < 2; h++) {
            const int idx = mt * 2 + h;
            const int rl  = row0 + mt * 16 + h * 8 + qr;
            const float inv = 1.f / l_i[idx];
#pragma unroll
            for (int nt = 0; nt < 4; nt++) {
                float2 w;
                w.x = U[mt][nt][2 * h] * inv;
                w.y = U[mt][nt][2 * h + 1] * inv;
                *(float2*)(Og + (size_t)rl * DH + col0 + nt * 8 + 2 * qc) = w;
            }
        }
}

extern "C" void kernel_launch(void* const* d_in, const int* in_sizes, int n_in,
                              void* d_out, int out_size)
{
    const float* Q = (const float*)d_in[0];
    const float* K = (const float*)d_in[1];
    const float* V = (const float*)d_in[2];
    float*       O = (float*)d_out;

    cudaFuncSetAttribute(fa_mma2, cudaFuncAttributeMaxDynamicSharedMemorySize, SMEM_BYTES);
    fa_mma2<<<BH * NQT, 512, SMEM_BYTES>>>(Q, K, V, O);
}